// round 8
// baseline (speedup 1.0000x reference)
#include <cuda_runtime.h>
#include <cuda_fp16.h>
#include <math.h>
#include <stdint.h>

// Problem constants
#define BB    2
#define TT    2048
#define CC    512
#define HH    8
#define DD    64
#define C3    1536
#define KSEL  4
#define GAMMA_F 2.5f
#define RHO_F   0.085f
#define TAUCLIP 5.0f
#define NROW  (BB*TT)       // 4096
#define KTOT  512

// ---------------- scratch (device globals) ---------------------------------
__device__ float g_qkv[(size_t)NROW * C3];        // 24 MB fp32
// fp16 operands
__device__ __half g_x_h[(size_t)NROW * KTOT];     // x hi
__device__ __half g_x_l[(size_t)NROW * KTOT];     // x lo
__device__ __half g_wqt[(size_t)C3 * KTOT];       // Wqkv^T fp16
__device__ __half g_wpt[(size_t)CC * KTOT];       // Wproj^T fp16
__device__ __half g_ao_h[(size_t)NROW * KTOT];    // attn_out hi
__device__ __half g_ao_l[(size_t)NROW * KTOT];    // attn_out lo

// ===================== helpers ==============================================
__device__ __forceinline__ uint32_t smem_u32(const void* p) {
    uint32_t a;
    asm("{ .reg .u64 t; cvta.to.shared.u64 t, %1; cvt.u32.u64 %0, t; }" : "=r"(a) : "l"(p));
    return a;
}
__device__ __forceinline__ void ldsm_x4(uint32_t& r0, uint32_t& r1, uint32_t& r2, uint32_t& r3,
                                        uint32_t addr) {
    asm volatile("ldmatrix.sync.aligned.m8n8.x4.shared.b16 {%0,%1,%2,%3}, [%4];"
                 : "=r"(r0), "=r"(r1), "=r"(r2), "=r"(r3) : "r"(addr));
}
__device__ __forceinline__ void mma_fp16(float* d, const uint32_t* a, uint32_t b0, uint32_t b1) {
    asm volatile("mma.sync.aligned.m16n8k16.row.col.f32.f16.f16.f32 "
                 "{%0,%1,%2,%3}, {%4,%5,%6,%7}, {%8,%9}, {%0,%1,%2,%3};"
                 : "+f"(d[0]), "+f"(d[1]), "+f"(d[2]), "+f"(d[3])
                 : "r"(a[0]), "r"(a[1]), "r"(a[2]), "r"(a[3]), "r"(b0), "r"(b1));
}

// ===================== operand prep (vectorized) ============================
__global__ void convert_split_h(const float* __restrict__ in,
                                __half* __restrict__ hi, __half* __restrict__ lo, int n4) {
    int i = blockIdx.x * 256 + threadIdx.x;     // float4 index
    if (i < n4) {
        float4 v = reinterpret_cast<const float4*>(in)[i];
        __half2 h01 = __floats2half2_rn(v.x, v.y);
        __half2 h23 = __floats2half2_rn(v.z, v.w);
        __half2 l01 = __floats2half2_rn(v.x - __half2float(__low2half(h01)),
                                        v.y - __half2float(__high2half(h01)));
        __half2 l23 = __floats2half2_rn(v.z - __half2float(__low2half(h23)),
                                        v.w - __half2float(__high2half(h23)));
        reinterpret_cast<__half2*>(hi)[i * 2]     = h01;
        reinterpret_cast<__half2*>(hi)[i * 2 + 1] = h23;
        reinterpret_cast<__half2*>(lo)[i * 2]     = l01;
        reinterpret_cast<__half2*>(lo)[i * 2 + 1] = l23;
    }
}

// W [K,N] fp32 -> [N,K] fp16
__global__ void transpose_half(const float* __restrict__ W,
                               __half* __restrict__ out, int K, int N) {
    __shared__ float tile[32][33];
    int n0 = blockIdx.x * 32, k0 = blockIdx.y * 32;
    int tx = threadIdx.x, ty = threadIdx.y;
    #pragma unroll
    for (int i = 0; i < 32; i += 8)
        tile[ty + i][tx] = W[(size_t)(k0 + ty + i) * N + n0 + tx];
    __syncthreads();
    #pragma unroll
    for (int i = 0; i < 32; i += 8)
        out[(size_t)(n0 + ty + i) * K + k0 + tx] = __float2half(tile[tx][ty + i]);
}

// ===================== K64 / 2-stage / swizzled GEMM core ===================
// BM=128, BN=128, 8 warps (4m x 2n), warp 32x64. Tiles: 128 rows x 128B,
// XOR swizzle: unit' = unit ^ (row & 7).
#define Q64_TILE 16384
#define Q64_STAGE (3 * Q64_TILE)     // Ah, Al, Bh
#define Q64_SMEM (2 * Q64_STAGE)     // 98304
#define Q64_NCH 8                    // 512 / 64

__device__ __forceinline__ void q64_load(
    uint32_t sm_base, int stage, int c, int m0, int n0, int tid, bool use_lo,
    const __half* __restrict__ Ah, const __half* __restrict__ Al,
    const __half* __restrict__ Bh)
{
    if (c < Q64_NCH) {
        uint32_t sbase = sm_base + stage * Q64_STAGE;
        const int k0 = c * 64;
        #pragma unroll
        for (int i = 0; i < 4; i++) {
            int u = tid + i * 256;           // 0..1023
            int r = u >> 3, cu = u & 7;
            const void* gp = Ah + (size_t)(m0 + r) * KTOT + k0 + cu * 8;
            uint32_t dst = sbase + r * 128 + ((cu ^ (r & 7)) << 4);
            asm volatile("cp.async.cg.shared.global [%0], [%1], 16;" :: "r"(dst), "l"(gp));
        }
        if (use_lo) {
            #pragma unroll
            for (int i = 0; i < 4; i++) {
                int u = tid + i * 256;
                int r = u >> 3, cu = u & 7;
                const void* gp = Al + (size_t)(m0 + r) * KTOT + k0 + cu * 8;
                uint32_t dst = sbase + Q64_TILE + r * 128 + ((cu ^ (r & 7)) << 4);
                asm volatile("cp.async.cg.shared.global [%0], [%1], 16;" :: "r"(dst), "l"(gp));
            }
        }
        #pragma unroll
        for (int i = 0; i < 4; i++) {
            int u = tid + i * 256;
            int r = u >> 3, cu = u & 7;
            const void* gp = Bh + (size_t)(n0 + r) * KTOT + k0 + cu * 8;
            uint32_t dst = sbase + 2 * Q64_TILE + r * 128 + ((cu ^ (r & 7)) << 4);
            asm volatile("cp.async.cg.shared.global [%0], [%1], 16;" :: "r"(dst), "l"(gp));
        }
    }
    asm volatile("cp.async.commit_group;" ::: "memory");
}

// Shared mainloop + epilogue. N_out = output row stride.
template<bool USE_LO_TMPL, bool LO_DYNAMIC>
__device__ __forceinline__ void gemm64_body(
    uint32_t sm_base, int m0, int n0, int tid, bool use_lo_dyn,
    const __half* __restrict__ Ah, const __half* __restrict__ Al,
    const __half* __restrict__ Bh,
    const float* __restrict__ bias, float* __restrict__ Cout, int N_out)
{
    const int wid = tid >> 5, lane = tid & 31;
    const int wm = wid >> 1, wn = wid & 1;
    const bool use_lo = LO_DYNAMIC ? use_lo_dyn : USE_LO_TMPL;

    float acc[2][8][4];
    #pragma unroll
    for (int i = 0; i < 2; i++)
        #pragma unroll
        for (int j = 0; j < 8; j++)
            #pragma unroll
            for (int l = 0; l < 4; l++) acc[i][j][l] = 0.f;

    q64_load(sm_base, 0, 0, m0, n0, tid, use_lo, Ah, Al, Bh);
    q64_load(sm_base, 1, 1, m0, n0, tid, use_lo, Ah, Al, Bh);

    const int lrow = lane & 15;
    const int lu8 = (lane >> 4);

    for (int c = 0; c < Q64_NCH; c++) {
        asm volatile("cp.async.wait_group 1;" ::: "memory");
        __syncthreads();
        const uint32_t stg = sm_base + (c & 1) * Q64_STAGE;

        #pragma unroll
        for (int kk = 0; kk < 4; kk++) {
            const int ubase = kk * 2 + lu8;
            uint32_t ah[2][4], al[2][4];
            #pragma unroll
            for (int im = 0; im < 2; im++) {
                int r = wm * 32 + im * 16 + lrow;
                uint32_t ra = stg + r * 128 + ((ubase ^ (r & 7)) << 4);
                ldsm_x4(ah[im][0], ah[im][1], ah[im][2], ah[im][3], ra);
                if (use_lo)
                    ldsm_x4(al[im][0], al[im][1], al[im][2], al[im][3], ra + Q64_TILE);
            }
            #pragma unroll
            for (int jn = 0; jn < 4; jn++) {
                int r = wn * 64 + jn * 16 + lrow;
                uint32_t rb = stg + 2 * Q64_TILE + r * 128 + ((ubase ^ (r & 7)) << 4);
                uint32_t bh[4];
                ldsm_x4(bh[0], bh[1], bh[2], bh[3], rb);
                #pragma unroll
                for (int im = 0; im < 2; im++) {
                    mma_fp16(acc[im][jn * 2],     ah[im], bh[0], bh[2]);
                    mma_fp16(acc[im][jn * 2 + 1], ah[im], bh[1], bh[3]);
                    if (use_lo) {
                        mma_fp16(acc[im][jn * 2],     al[im], bh[0], bh[2]);
                        mma_fp16(acc[im][jn * 2 + 1], al[im], bh[1], bh[3]);
                    }
                }
            }
        }
        __syncthreads();
        q64_load(sm_base, c & 1, c + 2, m0, n0, tid, use_lo, Ah, Al, Bh);
    }

    #pragma unroll
    for (int im = 0; im < 2; im++) {
        int rbase = m0 + wm * 32 + im * 16 + (lane >> 2);
        #pragma unroll
        for (int jf = 0; jf < 8; jf++) {
            int col = n0 + wn * 64 + jf * 8 + (lane & 3) * 2;
            float2 b2 = *reinterpret_cast<const float2*>(bias + col);
            float2 o0, o1;
            o0.x = acc[im][jf][0] + b2.x; o0.y = acc[im][jf][1] + b2.y;
            o1.x = acc[im][jf][2] + b2.x; o1.y = acc[im][jf][3] + b2.y;
            *reinterpret_cast<float2*>(Cout + (size_t)rbase * N_out + col) = o0;
            *reinterpret_cast<float2*>(Cout + (size_t)(rbase + 8) * N_out + col) = o1;
        }
    }
}

// QKV: hi for all cols, lo only for V cols (n0 >= 1024); heavy tiles first.
__global__ __launch_bounds__(256, 2) void qkv_gemm64(
    const __half* __restrict__ Ah, const __half* __restrict__ Al,
    const __half* __restrict__ Bh,
    const float* __restrict__ bias, float* __restrict__ Cout)
{
    extern __shared__ char smem[];
    const uint32_t sm_base = smem_u32(smem);
    const int m0 = blockIdx.y * 128;
    const int n0 = ((blockIdx.x + 8) % 12) * 128;
    gemm64_body<false, true>(sm_base, m0, n0, threadIdx.x, n0 >= 2 * CC,
                             Ah, Al, Bh, bias, Cout, C3);
}

// proj: 2-term always.
__global__ __launch_bounds__(256, 2) void proj_gemm64(
    const __half* __restrict__ Ah, const __half* __restrict__ Al,
    const __half* __restrict__ Bh,
    const float* __restrict__ bias, float* __restrict__ Cout)
{
    extern __shared__ char smem[];
    const uint32_t sm_base = smem_u32(smem);
    const int m0 = blockIdx.y * 128;
    const int n0 = blockIdx.x * 128;
    gemm64_body<true, false>(sm_base, m0, n0, threadIdx.x, true,
                             Ah, Al, Bh, bias, Cout, CC);
}

// ===================== fused topk + attention + tau_new =====================
__global__ __launch_bounds__(256) void attn_topk_fused(const float* __restrict__ tau,
                                                       float* __restrict__ out_tau) {
    const int row = blockIdx.x;
    const int tid = threadIdx.x;
    const int warp = tid >> 5, lane = tid & 31;   // warp == head
    const int b = row / TT;

    __shared__ float stau[TT];                    // 8 KB
    __shared__ unsigned long long sk[256 * 4];    // 8 KB
    __shared__ float red[256];
    __shared__ int   sidx[KSEL];
    __shared__ float sbias[KSEL];
    __shared__ float stval[KSEL];
    __shared__ float ssig[KSEL];
    __shared__ float sinv;

    // ---- load tau row + per-thread top4 + sum ----
    const float4* tin = reinterpret_cast<const float4*>(tau + (size_t)row * TT);
    unsigned long long k0 = 0, k1 = 0, k2 = 0, k3 = 0;
    float sum = 0.f;
    #pragma unroll
    for (int t = 0; t < 2; t++) {
        int i = tid + t * 256;                    // float4 index
        float4 v = tin[i];
        reinterpret_cast<float4*>(stau)[i] = v;
        float vv[4] = {v.x, v.y, v.z, v.w};
        #pragma unroll
        for (int j = 0; j < 4; j++) {
            sum += vv[j];
            int col = i * 4 + j;
            unsigned long long key =
                ((unsigned long long)__float_as_uint(vv[j]) << 32) | (unsigned)(0x7FFFFFFF - col);
            if (key > k3) {
                if (key > k0)      { k3 = k2; k2 = k1; k1 = k0; k0 = key; }
                else if (key > k1) { k3 = k2; k2 = k1; k1 = key; }
                else if (key > k2) { k3 = k2; k2 = key; }
                else               { k3 = key; }
            }
        }
    }
    sk[tid * 4 + 0] = k0; sk[tid * 4 + 1] = k1;
    sk[tid * 4 + 2] = k2; sk[tid * 4 + 3] = k3;
    red[tid] = sum;
    __syncthreads();

    for (int s = 128; s > 0; s >>= 1) {
        if (tid < s) {
            red[tid] += red[tid + s];
            unsigned long long a[4], bb[4], o[4];
            #pragma unroll
            for (int t = 0; t < 4; t++) { a[t] = sk[tid * 4 + t]; bb[t] = sk[(tid + s) * 4 + t]; }
            int ia = 0, ib = 0;
            #pragma unroll
            for (int t = 0; t < 4; t++) {
                if (a[ia] >= bb[ib]) o[t] = a[ia++];
                else                 o[t] = bb[ib++];
            }
            #pragma unroll
            for (int t = 0; t < 4; t++) sk[tid * 4 + t] = o[t];
        }
        __syncthreads();
    }
    if (tid < KSEL) {
        int id = 0x7FFFFFFF - (int)(sk[tid] & 0xFFFFFFFFu);
        float tv = stau[id];
        sidx[tid]  = id;
        stval[tid] = tv;
        sbias[tid] = GAMMA_F * logf(tv + 1e-8f);
        ssig[tid]  = 0.f;
    }
    __syncthreads();

    // ---- sparse attention ----
    const float* qp = g_qkv + (size_t)row * C3 + warp * DD;
    const float q0 = qp[lane], q1 = qp[lane + 32];

    float logit[KSEL];
    #pragma unroll
    for (int j = 0; j < KSEL; j++) {
        int s = sidx[j];
        const float* kp = g_qkv + (size_t)(b * TT + s) * C3 + CC + warp * DD;
        float p = q0 * kp[lane] + q1 * kp[lane + 32];
        #pragma unroll
        for (int o = 16; o > 0; o >>= 1) p += __shfl_xor_sync(0xffffffffu, p, o);
        logit[j] = p * 0.125f + sbias[j];
    }
    float m = fmaxf(fmaxf(logit[0], logit[1]), fmaxf(logit[2], logit[3]));
    float e[KSEL], se = 0.f;
    #pragma unroll
    for (int j = 0; j < KSEL; j++) { e[j] = expf(logit[j] - m); se += e[j]; }
    float inv = 1.f / se;
    float w[KSEL];
    #pragma unroll
    for (int j = 0; j < KSEL; j++) w[j] = e[j] * inv;

    float o0 = 0.f, o1 = 0.f;
    #pragma unroll
    for (int j = 0; j < KSEL; j++) {
        const float* vp = g_qkv + (size_t)(b * TT + sidx[j]) * C3 + 2 * CC + warp * DD;
        o0 = fmaf(w[j], vp[lane], o0);
        o1 = fmaf(w[j], vp[lane + 32], o1);
    }
    size_t obase = (size_t)row * KTOT + warp * DD;
    __half h0 = __float2half(o0);
    __half h1 = __float2half(o1);
    g_ao_h[obase + lane]      = h0;
    g_ao_h[obase + lane + 32] = h1;
    g_ao_l[obase + lane]      = __float2half(o0 - __half2float(h0));
    g_ao_l[obase + lane + 32] = __float2half(o1 - __half2float(h1));

    if (lane == 0) {
        #pragma unroll
        for (int j = 0; j < KSEL; j++) atomicAdd(&ssig[j], w[j] * (1.0f / HH));
    }
    __syncthreads();
    if (tid == 0) {
        float rs = red[0] * (1.0f - RHO_F);
        #pragma unroll
        for (int j = 0; j < KSEL; j++) { float s = ssig[j]; rs += s * s * s; }
        sinv = 1.f / (rs + 1e-8f);
    }
    __syncthreads();

    // ---- tau_new: scale from smem + patch ----
    const float f = (1.0f - RHO_F) * sinv;
    float4* tout = reinterpret_cast<float4*>(out_tau + (size_t)row * TT);
    #pragma unroll
    for (int t = 0; t < 2; t++) {
        int i = tid + t * 256;
        float4 v = reinterpret_cast<const float4*>(stau)[i];
        v.x = fminf(v.x * f, TAUCLIP);
        v.y = fminf(v.y * f, TAUCLIP);
        v.z = fminf(v.z * f, TAUCLIP);
        v.w = fminf(v.w * f, TAUCLIP);
        tout[i] = v;
    }
    __syncthreads();
    if (tid < KSEL) {
        float s = ssig[tid];
        float v = stval[tid] * (1.0f - RHO_F) + s * s * s;
        out_tau[(size_t)row * TT + sidx[tid]] = fminf(v * sinv, TAUCLIP);
    }
}

// ===================== launch ===============================================
extern "C" void kernel_launch(void* const* d_in, const int* in_sizes, int n_in,
                              void* d_out, int out_size) {
    const float* x     = (const float*)d_in[0];
    const float* tau   = (const float*)d_in[1];
    const float* Wqkv  = (const float*)d_in[2];
    const float* bqkv  = (const float*)d_in[3];
    const float* Wproj = (const float*)d_in[4];
    const float* bproj = (const float*)d_in[5];

    float* out_main = (float*)d_out;
    float* out_tau  = out_main + (size_t)NROW * CC;

    void *p_qkv, *p_xh, *p_xl, *p_wqt, *p_wpt, *p_aoh, *p_aol;
    cudaGetSymbolAddress(&p_qkv, g_qkv);
    cudaGetSymbolAddress(&p_xh, g_x_h);   cudaGetSymbolAddress(&p_xl, g_x_l);
    cudaGetSymbolAddress(&p_wqt, g_wqt);  cudaGetSymbolAddress(&p_wpt, g_wpt);
    cudaGetSymbolAddress(&p_aoh, g_ao_h); cudaGetSymbolAddress(&p_aol, g_ao_l);

    cudaFuncSetAttribute(qkv_gemm64, cudaFuncAttributeMaxDynamicSharedMemorySize, Q64_SMEM);
    cudaFuncSetAttribute(proj_gemm64, cudaFuncAttributeMaxDynamicSharedMemorySize, Q64_SMEM);

    // 1-3. operand prep
    convert_split_h<<<(NROW * KTOT / 4) / 256, 256>>>(x, (__half*)p_xh, (__half*)p_xl, NROW * KTOT / 4);
    transpose_half<<<dim3(C3 / 32, KTOT / 32), dim3(32, 8)>>>(Wqkv, (__half*)p_wqt, KTOT, C3);
    transpose_half<<<dim3(CC / 32, KTOT / 32), dim3(32, 8)>>>(Wproj, (__half*)p_wpt, KTOT, CC);

    // 4. QKV GEMM (K-chunk 64, 2-stage, swizzled)
    qkv_gemm64<<<dim3(12, NROW / 128), 256, Q64_SMEM>>>(
        (const __half*)p_xh, (const __half*)p_xl, (const __half*)p_wqt,
        bqkv, (float*)p_qkv);

    // 5. fused: topk + sparse attention + tau_new
    attn_topk_fused<<<NROW, 256>>>(tau, out_tau);

    // 6. proj GEMM (K64 structure, 2-term) -> d_out
    proj_gemm64<<<dim3(CC / 128, NROW / 128), 256, Q64_SMEM>>>(
        (const __half*)p_aoh, (const __half*)p_aol, (const __half*)p_wpt,
        bproj, out_main);
}